// round 1
// baseline (speedup 1.0000x reference)
#include <cuda_runtime.h>
#include <math.h>

#define BB 4
#define SEQ 4096
#define DM 1024
#define KCH 256
#define ROWS (BB*SEQ)          // 16384
#define NPROJ (6*KCH)          // 1536
#define RHO_PAD 1024
#define CHUNK 2048

// ---------------- scratch (global device memory, allocation-free) ----------
__device__ __align__(16) float g_proj [(size_t)ROWS*NPROJ];   // (b,n, 6K)
__device__ __align__(16) float g_pq   [(size_t)ROWS*KCH];     // (b,n,K)
__device__ __align__(16) float g_alpha[(size_t)BB*KCH*SEQ];   // (b,k,n)
__device__ __align__(16) float g_dr   [(size_t)BB*KCH*SEQ];   // (b,k,n)
__device__ __align__(16) float g_di   [(size_t)BB*KCH*SEQ];   // (b,k,n)
__device__ __align__(16) float g_cosb [(size_t)ROWS*KCH];     // (b,n,k)
__device__ __align__(16) float g_sinb [(size_t)ROWS*KCH];
__device__ __align__(16) float g_betab[(size_t)ROWS*KCH];
__device__ __align__(16) float g_gb   [(size_t)ROWS*KCH];
__device__ __align__(16) float g_rr   [(size_t)ROWS*KCH];     // (b,n,k)
__device__ __align__(16) float g_ri   [(size_t)ROWS*KCH];
__device__ __align__(16) float g_rho  [(size_t)ROWS*RHO_PAD]; // padded 1022->1024
__device__ __align__(16) float g_wresp[(size_t)DM*RHO_PAD];   // padded W_res

// ---------------- helpers --------------------------------------------------
__device__ __forceinline__ float sigm(float x) { return 1.0f / (1.0f + expf(-x)); }
__device__ __forceinline__ float softplusf(float x) {
    return (x > 20.0f) ? x : log1pf(expf(x));
}

// ---------------- pad W_res (1024 x 1022) -> (1024 x 1024) ----------------
__global__ void pad_wres_kernel(const float* __restrict__ W) {
    int i = blockIdx.x * 256 + threadIdx.x;          // 0 .. 1024*1024-1
    int d = i >> 10, j = i & 1023;
    g_wresp[i] = (j < 1022) ? W[(size_t)d * 1022 + j] : 0.0f;
}

// ---------------- generic fp32 GEMM: C[m,n] = scale * sum_k A[m,k]W[n,k] (+bias[n])
// mode 0: C = g_proj (A ext)     mode 1: C = g_pq (A ext)
// mode 2: A = g_rho, W = g_wresp, C ext (d_out)
__global__ __launch_bounds__(256) void gemm_nt_kernel(
    const float* __restrict__ A_ext, const float* __restrict__ W_ext,
    const float* __restrict__ bias, const float* __restrict__ scale_ptr,
    float* __restrict__ C_ext, int N, int Kd, int mode)
{
    const float* A = (mode == 2) ? g_rho   : A_ext;
    const float* W = (mode == 2) ? g_wresp : W_ext;
    float*       C = (mode == 0) ? g_proj  : ((mode == 1) ? g_pq : C_ext);

    __shared__ float As[16][128];
    __shared__ float Ws[16][128];

    int tid = threadIdx.x;
    int m0 = blockIdx.y * 128, n0 = blockIdx.x * 128;
    int tm = (tid & 15) * 8, tn = (tid >> 4) * 8;

    float acc[8][8];
#pragma unroll
    for (int i = 0; i < 8; i++)
#pragma unroll
        for (int j = 0; j < 8; j++) acc[i][j] = 0.0f;

    for (int kt = 0; kt < Kd; kt += 16) {
#pragma unroll
        for (int it = 0; it < 2; it++) {
            int l = tid + it * 256;          // 0..511
            int row = l >> 2, kq = l & 3;
            float4 va = *(const float4*)(A + (size_t)(m0 + row) * Kd + kt + kq * 4);
            As[kq * 4 + 0][row] = va.x; As[kq * 4 + 1][row] = va.y;
            As[kq * 4 + 2][row] = va.z; As[kq * 4 + 3][row] = va.w;
            float4 vb = *(const float4*)(W + (size_t)(n0 + row) * Kd + kt + kq * 4);
            Ws[kq * 4 + 0][row] = vb.x; Ws[kq * 4 + 1][row] = vb.y;
            Ws[kq * 4 + 2][row] = vb.z; Ws[kq * 4 + 3][row] = vb.w;
        }
        __syncthreads();
#pragma unroll
        for (int kk = 0; kk < 16; kk++) {
            float4 a0 = *(const float4*)&As[kk][tm];
            float4 a1 = *(const float4*)&As[kk][tm + 4];
            float4 b0 = *(const float4*)&Ws[kk][tn];
            float4 b1 = *(const float4*)&Ws[kk][tn + 4];
            float av[8] = {a0.x, a0.y, a0.z, a0.w, a1.x, a1.y, a1.z, a1.w};
            float bv[8] = {b0.x, b0.y, b0.z, b0.w, b1.x, b1.y, b1.z, b1.w};
#pragma unroll
            for (int i = 0; i < 8; i++)
#pragma unroll
                for (int j = 0; j < 8; j++)
                    acc[i][j] = fmaf(av[i], bv[j], acc[i][j]);
        }
        __syncthreads();
    }

    float sc = scale_ptr ? *scale_ptr : 1.0f;
#pragma unroll
    for (int i = 0; i < 8; i++) {
#pragma unroll
        for (int j = 0; j < 8; j++) {
            float v = acc[i][j] * sc;
            if (bias) v += bias[n0 + tn + j];
            C[(size_t)(m0 + tm + i) * N + n0 + tn + j] = v;
        }
    }
}

// ---------------- prescan: activations + transpose for the scan -----------
// grid 4096 blocks: b(4) x n-tile(128) x k-tile(8); 256 threads (32 k x 8 n)
__global__ __launch_bounds__(256) void prescan_kernel() {
    __shared__ float t_a [32][33];   // [n_local][k_local]
    __shared__ float t_dr[32][33];
    __shared__ float t_di[32][33];

    int bk = blockIdx.x;
    int kb = bk & 7, nb = (bk >> 3) & 127, b = bk >> 10;
    int k0 = kb * 32, n0 = nb * 32;
    int tx = threadIdx.x & 31;       // k_local (load phase) / n_local (store phase)
    int ty = threadIdx.x >> 5;       // 0..7

#pragma unroll
    for (int nn = 0; nn < 4; nn++) {
        int nl = nn * 8 + ty;
        int n = n0 + nl;
        size_t row = (size_t)(b * SEQ + n);
        size_t pb = row * NPROJ + k0 + tx;
        float pa  = g_proj[pb];
        float pw  = g_proj[pb + KCH];
        float pp  = g_proj[pb + 2 * KCH];
        float pal = g_proj[pb + 3 * KCH];
        float pg  = g_proj[pb + 4 * KCH];
        float pbe = g_proj[pb + 5 * KCH];

        float Aamp  = 3.0f * sigm(pa);
        float omega = softplusf(pw);
        float alpha = sigm(pal);
        float gg    = sigm(pg);
        float bee   = sigm(pbe);
        float pos   = log1pf((float)n);
        float angle = fmaf(omega, pos, pp);
        float sn, cs;
        sincosf(angle, &sn, &cs);

        size_t ob = row * KCH + k0 + tx;
        g_cosb[ob] = cs; g_sinb[ob] = sn; g_betab[ob] = bee; g_gb[ob] = gg;

        float oma = 1.0f - alpha;
        t_a [nl][tx] = alpha;
        t_dr[nl][tx] = oma * Aamp * cs;
        t_di[nl][tx] = oma * Aamp * sn;
    }
    __syncthreads();
#pragma unroll
    for (int nn = 0; nn < 4; nn++) {
        int kl = nn * 8 + ty;
        size_t ob = ((size_t)(b * KCH + k0 + kl)) * SEQ + n0 + tx;   // (b,k,n)
        g_alpha[ob] = t_a [tx][kl];
        g_dr   [ob] = t_dr[tx][kl];
        g_di   [ob] = t_di[tx][kl];
    }
}

// ---------------- scan: r_t = alpha_t * r_{t-1} + drive_t over n -----------
// grid 1024 blocks (one per (b,k)); 256 threads; 2 chunks of 2048
__global__ __launch_bounds__(256) void scan_kernel() {
    __shared__ float s_a[CHUNK], s_br[CHUNK], s_bi[CHUNK];
    __shared__ float sc_a[256], sc_r[256], sc_i[256];

    int bk = blockIdx.x;
    int b = bk >> 8, k = bk & 255;
    size_t base = (size_t)bk * SEQ;
    int tid = threadIdx.x;
    float carry_r = 0.0f, carry_i = 0.0f;

    for (int c = 0; c < SEQ / CHUNK; c++) {
        for (int idx = tid; idx < CHUNK; idx += 256) {
            s_a [idx] = g_alpha[base + c * CHUNK + idx];
            s_br[idx] = g_dr   [base + c * CHUNK + idx];
            s_bi[idx] = g_di   [base + c * CHUNK + idx];
        }
        __syncthreads();

        int j0 = tid * 8;
        float Asg = 1.0f, Br = 0.0f, Bi = 0.0f;
#pragma unroll
        for (int j = 0; j < 8; j++) {
            float a = s_a[j0 + j];
            Asg *= a;
            Br = fmaf(a, Br, s_br[j0 + j]);
            Bi = fmaf(a, Bi, s_bi[j0 + j]);
        }
        sc_a[tid] = Asg; sc_r[tid] = Br; sc_i[tid] = Bi;
        __syncthreads();

        for (int off = 1; off < 256; off <<= 1) {
            float pa = 1.0f, pr = 0.0f, pi = 0.0f;
            if (tid >= off) { pa = sc_a[tid - off]; pr = sc_r[tid - off]; pi = sc_i[tid - off]; }
            float ca = sc_a[tid], cr = sc_r[tid], ci = sc_i[tid];
            __syncthreads();
            sc_a[tid] = pa * ca;
            sc_r[tid] = fmaf(ca, pr, cr);
            sc_i[tid] = fmaf(ca, pi, ci);
            __syncthreads();
        }

        float exa = (tid > 0) ? sc_a[tid - 1] : 1.0f;
        float exr = (tid > 0) ? sc_r[tid - 1] : 0.0f;
        float exi = (tid > 0) ? sc_i[tid - 1] : 0.0f;
        float rr = fmaf(exa, carry_r, exr);
        float ri = fmaf(exa, carry_i, exi);
        float ncr = fmaf(sc_a[255], carry_r, sc_r[255]);
        float nci = fmaf(sc_a[255], carry_i, sc_i[255]);

#pragma unroll
        for (int j = 0; j < 8; j++) {
            float a = s_a[j0 + j];
            rr = fmaf(a, rr, s_br[j0 + j]);
            ri = fmaf(a, ri, s_bi[j0 + j]);
            int n = c * CHUNK + j0 + j;
            size_t o = ((size_t)(b * SEQ + n)) * KCH + k;   // (b,n,k)
            g_rr[o] = rr;
            g_ri[o] = ri;
        }
        carry_r = ncr; carry_i = nci;
        __syncthreads();
    }
}

// ---------------- postscan: erase/norm/demod/gate/SCPM -> rho (padded) -----
__global__ __launch_bounds__(256) void postscan_kernel(const float* __restrict__ lam_ptr) {
    __shared__ float sre[256], simm[256], sgg[256];
    int row = blockIdx.x;           // b*4096 + n
    int k = threadIdx.x;
    size_t o = (size_t)row * KCH + k;

    float rr = g_rr[o], ri = g_ri[o];
    float cs = g_cosb[o], sn = g_sinb[o];
    float be = g_betab[o], gg = g_gb[o];
    float pq = g_pq[o];

    float readout = fmaf(rr, cs, ri * sn);
    rr = fmaf(-be * readout, cs, rr);
    ri = fmaf(-be * readout, sn, ri);

    float mod = sqrtf(fmaf(rr, rr, fmaf(ri, ri, 1e-8f)));
    float scl = fmaxf(mod, 1.0f);
    rr /= scl; ri /= scl;

    float rre = fmaf(rr, cs, ri * sn);
    float rim = fmaf(-rr, sn, ri * cs);

    float rn = sqrtf(fmaf(rre, rre, fmaf(rim, rim, 1e-8f)));
    float ps, pc;
    sincosf(pq, &ps, &pc);
    float align = (rre * pc + rim * ps) / rn;
    float lam = *lam_ptr;
    float gate = 1.0f / (1.0f + expf(-lam * align));
    rre *= gate; rim *= gate;

    sre[k] = rre; simm[k] = rim; sgg[k] = gg;
    __syncthreads();

    size_t ob = (size_t)row * RHO_PAD;
    g_rho[ob + k]       = gg * rre;
    g_rho[ob + 256 + k] = gg * rim;
    if (k < 255) {
        float are = sre[k], aim = simm[k], bre = sre[k + 1], bim = simm[k + 1];
        float xre = are * bre - aim * bim;
        float xim = are * bim + aim * bre;
        float gc = 0.5f * (sgg[k] + sgg[k + 1]);
        g_rho[ob + 512 + k] = gc * xre;
        g_rho[ob + 767 + k] = gc * xim;
    } else {
        g_rho[ob + 1022] = 0.0f;
        g_rho[ob + 1023] = 0.0f;
    }
}

// ---------------- launch ---------------------------------------------------
extern "C" void kernel_launch(void* const* d_in, const int* in_sizes, int n_in,
                              void* d_out, int out_size) {
    const float* x   = (const float*)d_in[0];
    const float* Wp  = (const float*)d_in[1];
    const float* bp  = (const float*)d_in[2];
    const float* Wr  = (const float*)d_in[3];
    const float* Wph = (const float*)d_in[4];
    const float* bph = (const float*)d_in[5];
    const float* lam = (const float*)d_in[6];
    const float* rs  = (const float*)d_in[7];
    float* out = (float*)d_out;

    pad_wres_kernel<<<(DM * RHO_PAD) / 256, 256>>>(Wr);

    // proj = x @ W_proj^T + b_proj   (writes g_proj, mode 0)
    gemm_nt_kernel<<<dim3(NPROJ / 128, ROWS / 128), 256>>>(
        x, Wp, bp, nullptr, nullptr, NPROJ, DM, 0);

    // phase_query = x @ W_phase^T + b_phase   (writes g_pq, mode 1)
    gemm_nt_kernel<<<dim3(KCH / 128, ROWS / 128), 256>>>(
        x, Wph, bph, nullptr, nullptr, KCH, DM, 1);

    prescan_kernel<<<4096, 256>>>();
    scan_kernel<<<BB * KCH, 256>>>();
    postscan_kernel<<<ROWS, 256>>>(lam);

    // out = res_scale * rho @ W_res^T   (reads g_rho/g_wresp, mode 2)
    gemm_nt_kernel<<<dim3(DM / 128, ROWS / 128), 256>>>(
        nullptr, nullptr, nullptr, rs, out, DM, RHO_PAD, 2);
}

// round 6
// speedup vs baseline: 2.5569x; 2.5569x over previous
#include <cuda_runtime.h>
#include <cuda_bf16.h>
#include <math.h>
#include <stdint.h>

#define BB 4
#define SEQ 4096
#define DM 1024
#define K3 3072                 // 3x split concatenated K
#define KB3 (K3*2)              // bytes per row (6144)
#define KCH 256
#define ROWS (BB*SEQ)           // 16384
#define NPROJ (6*KCH)           // 1536
#define CHUNK 2048
#define NKIT (K3/64)            // 48 k-tiles
#define GSMEM 65536             // 2 stages x (16KB A + 16KB B)

// ---------------- scratch (global device memory, allocation-free) ----------
__device__ __align__(16) float g_proj [(size_t)ROWS*NPROJ];
__device__ __align__(16) float g_pq   [(size_t)ROWS*KCH];
__device__ __align__(16) float g_alpha[(size_t)BB*KCH*SEQ];
__device__ __align__(16) float g_dr   [(size_t)BB*KCH*SEQ];
__device__ __align__(16) float g_di   [(size_t)BB*KCH*SEQ];
__device__ __align__(16) float g_cosb [(size_t)ROWS*KCH];
__device__ __align__(16) float g_sinb [(size_t)ROWS*KCH];
__device__ __align__(16) float g_betab[(size_t)ROWS*KCH];
__device__ __align__(16) float g_gb   [(size_t)ROWS*KCH];
__device__ __align__(16) float g_rr   [(size_t)ROWS*KCH];
__device__ __align__(16) float g_ri   [(size_t)ROWS*KCH];

// bf16 concatenated-split operands: A pattern [hi|hi|lo], B pattern [hi|lo|hi]
__device__ __align__(16) __nv_bfloat16 g_xcat  [(size_t)ROWS*K3];
__device__ __align__(16) __nv_bfloat16 g_wpcat [(size_t)NPROJ*K3];
__device__ __align__(16) __nv_bfloat16 g_wqcat [(size_t)KCH*K3];
__device__ __align__(16) __nv_bfloat16 g_wrcat [(size_t)DM*K3];
__device__ __align__(16) __nv_bfloat16 g_rhocat[(size_t)ROWS*K3];

// ---------------- helpers --------------------------------------------------
__device__ __forceinline__ uint32_t smem_u32(const void* p) {
    uint32_t a;
    asm("{ .reg .u64 t; cvta.to.shared.u64 t, %1; cvt.u32.u64 %0, t; }" : "=r"(a) : "l"(p));
    return a;
}
__device__ __forceinline__ void cp16(uint32_t s, const void* g) {
    asm volatile("cp.async.cg.shared.global [%0], [%1], 16;" :: "r"(s), "l"(g) : "memory");
}
#define CP_COMMIT() asm volatile("cp.async.commit_group;" ::: "memory")

__device__ __forceinline__ void ldsm4(uint32_t* r, uint32_t addr) {
    asm volatile("ldmatrix.sync.aligned.m8n8.x4.shared.b16 {%0,%1,%2,%3}, [%4];"
                 : "=r"(r[0]), "=r"(r[1]), "=r"(r[2]), "=r"(r[3]) : "r"(addr));
}
__device__ __forceinline__ void mma16816(float* c, const uint32_t* a, const uint32_t* b) {
    asm volatile("mma.sync.aligned.m16n8k16.row.col.f32.bf16.bf16.f32 "
                 "{%0,%1,%2,%3}, {%4,%5,%6,%7}, {%8,%9}, {%0,%1,%2,%3};"
                 : "+f"(c[0]), "+f"(c[1]), "+f"(c[2]), "+f"(c[3])
                 : "r"(a[0]), "r"(a[1]), "r"(a[2]), "r"(a[3]), "r"(b[0]), "r"(b[1]));
}
__device__ __forceinline__ float sigm(float x) { return 1.0f / (1.0f + expf(-x)); }
__device__ __forceinline__ float softplusf(float x) { return (x > 20.0f) ? x : log1pf(expf(x)); }
__device__ __forceinline__ void bsplit(float v, __nv_bfloat16& h, __nv_bfloat16& l) {
    h = __float2bfloat16(v);
    l = __float2bfloat16(v - __bfloat162float(h));
}

// ---------------- split fp32 (rows x 1024) -> bf16 concatenated (rows x 3072)
// which: 0=x(A), 1=W_proj(B), 2=W_phase(B)
__global__ void split_cat_kernel(const float4* __restrict__ src, int n4, int which) {
    int i = blockIdx.x * 256 + threadIdx.x;
    if (i >= n4) return;
    float4 v = src[i];
    __nv_bfloat16* dst = (which == 0) ? g_xcat : ((which == 1) ? g_wpcat : g_wqcat);
    int isA = (which == 0);
    int row = i >> 8, q = i & 255;
    size_t base = (size_t)row * K3 + q * 4;
    __nv_bfloat16 h[4], l[4];
    bsplit(v.x, h[0], l[0]); bsplit(v.y, h[1], l[1]);
    bsplit(v.z, h[2], l[2]); bsplit(v.w, h[3], l[3]);
#pragma unroll
    for (int j = 0; j < 4; j++) {
        dst[base + j]        = h[j];
        dst[base + 1024 + j] = isA ? h[j] : l[j];
        dst[base + 2048 + j] = isA ? l[j] : h[j];
    }
}

// W_res (1024 x 1022) -> padded, B pattern
__global__ void wres_split_cat_kernel(const float* __restrict__ W) {
    int i = blockIdx.x * 256 + threadIdx.x;       // 0 .. 1024*1024-1
    int d = i >> 10, j = i & 1023;
    float v = (j < 1022) ? W[(size_t)d * 1022 + j] : 0.0f;
    __nv_bfloat16 h, l; bsplit(v, h, l);
    size_t base = (size_t)d * K3;
    g_wrcat[base + j]        = h;
    g_wrcat[base + 1024 + j] = l;
    g_wrcat[base + 2048 + j] = h;
}

// ---------------- HMMA GEMM: C[m,n] = sc * sum_k A[m,k]B[n,k] (+bias[n]) ----
// mode 0: A=g_xcat, B=g_wpcat, C=g_proj     mode 1: A=g_xcat, B=g_wqcat, C=g_pq
// mode 2: A=g_rhocat, B=g_wrcat, C=ext
__global__ __launch_bounds__(256, 1) void mma_gemm(
    const float* __restrict__ bias, const float* __restrict__ scale_ptr,
    float* __restrict__ C_ext, int Nt, int mode)
{
    extern __shared__ char smem[];
    const __nv_bfloat16 *A, *B; float* C;
    if (mode == 2)      { A = g_rhocat; B = g_wrcat; C = C_ext;  }
    else if (mode == 0) { A = g_xcat;   B = g_wpcat; C = g_proj; }
    else                { A = g_xcat;   B = g_wqcat; C = g_pq;   }

    uint32_t sb = smem_u32(smem);
    int tid = threadIdx.x, lane = tid & 31, wid = tid >> 5;
    int wm = wid >> 2, wn = wid & 3;               // warps 2(m) x 4(n)
    int m0 = blockIdx.y * 128, n0 = blockIdx.x * 128;

    const char* gA = (const char*)A + (size_t)m0 * KB3;
    const char* gB = (const char*)B + (size_t)n0 * KB3;

    // staging: thread t -> (row = t/8 + 32r, seg = t%8), 4 rounds each for A,B
    int srow = tid >> 3, sseg = tid & 7;
    uint32_t s_soff = (uint32_t)srow * 128 + (uint32_t)((sseg ^ (srow & 7)) * 16);
    size_t s_goff = (size_t)srow * KB3 + (size_t)sseg * 16;

    // ldmatrix lane geometry
    int rowA = wm * 64 + (lane & 15);              // + mi*16
    int segA = lane >> 4;                          // 0/1 within k16
    int xorA = rowA & 7;
    int rowBin = (lane & 7) + ((lane >> 4) << 3);  // + wn*32 + j2*16
    int segB = (lane >> 3) & 1;

    float acc[4][4][4];
#pragma unroll
    for (int mi = 0; mi < 4; mi++)
#pragma unroll
        for (int nj = 0; nj < 4; nj++)
#pragma unroll
            for (int q = 0; q < 4; q++) acc[mi][nj][q] = 0.0f;

    // prologue: stage k-tile 0 into buffer 0
    {
        const char* ga = gA; const char* gb = gB;
#pragma unroll
        for (int r = 0; r < 4; r++) {
            cp16(sb + s_soff + r * 4096,         ga + s_goff + (size_t)r * 32 * KB3);
            cp16(sb + 16384 + s_soff + r * 4096, gb + s_goff + (size_t)r * 32 * KB3);
        }
        CP_COMMIT();
    }

    for (int kt = 0; kt < NKIT; kt++) {
        if (kt + 1 < NKIT) {
            uint32_t bs = sb + ((kt + 1) & 1) * 32768;
            const char* ga = gA + (size_t)(kt + 1) * 128;
            const char* gb = gB + (size_t)(kt + 1) * 128;
#pragma unroll
            for (int r = 0; r < 4; r++) {
                cp16(bs + s_soff + r * 4096,         ga + s_goff + (size_t)r * 32 * KB3);
                cp16(bs + 16384 + s_soff + r * 4096, gb + s_goff + (size_t)r * 32 * KB3);
            }
            CP_COMMIT();
            asm volatile("cp.async.wait_group 1;" ::: "memory");
        } else {
            asm volatile("cp.async.wait_group 0;" ::: "memory");
        }
        __syncthreads();

        uint32_t bufA = sb + (kt & 1) * 32768;
        uint32_t bufB = bufA + 16384;
#pragma unroll
        for (int ks = 0; ks < 4; ks++) {
            uint32_t a[4][4], b[2][4];
#pragma unroll
            for (int mi = 0; mi < 4; mi++) {
                uint32_t addr = bufA + (uint32_t)(rowA + mi * 16) * 128
                              + (uint32_t)(((ks * 2 + segA) ^ xorA) * 16);
                ldsm4(a[mi], addr);
            }
#pragma unroll
            for (int j2 = 0; j2 < 2; j2++) {
                int rb = wn * 32 + j2 * 16 + rowBin;
                uint32_t addr = bufB + (uint32_t)rb * 128
                              + (uint32_t)(((ks * 2 + segB) ^ (rb & 7)) * 16);
                ldsm4(b[j2], addr);
            }
#pragma unroll
            for (int mi = 0; mi < 4; mi++) {
#pragma unroll
                for (int j2 = 0; j2 < 2; j2++) {
                    mma16816(acc[mi][j2 * 2],     a[mi], &b[j2][0]);
                    mma16816(acc[mi][j2 * 2 + 1], a[mi], &b[j2][2]);
                }
            }
        }
        __syncthreads();
    }

    // epilogue
    float sc = scale_ptr ? *scale_ptr : 1.0f;
#pragma unroll
    for (int mi = 0; mi < 4; mi++) {
#pragma unroll
        for (int nj = 0; nj < 4; nj++) {
            int row = m0 + wm * 64 + mi * 16 + (lane >> 2);
            int col = n0 + wn * 32 + nj * 8 + (lane & 3) * 2;
            float b0 = 0.0f, b1 = 0.0f;
            if (bias) { b0 = bias[col]; b1 = bias[col + 1]; }
            float2 v0 = make_float2(acc[mi][nj][0] * sc + b0, acc[mi][nj][1] * sc + b1);
            float2 v1 = make_float2(acc[mi][nj][2] * sc + b0, acc[mi][nj][3] * sc + b1);
            *(float2*)(C + (size_t)row * Nt + col)       = v0;
            *(float2*)(C + (size_t)(row + 8) * Nt + col) = v1;
        }
    }
}

// ---------------- prescan: activations + transpose for the scan -----------
__global__ __launch_bounds__(256) void prescan_kernel() {
    __shared__ float t_a [32][33];
    __shared__ float t_dr[32][33];
    __shared__ float t_di[32][33];

    int bk = blockIdx.x;
    int kb = bk & 7, nb = (bk >> 3) & 127, b = bk >> 10;
    int k0 = kb * 32, n0 = nb * 32;
    int tx = threadIdx.x & 31;
    int ty = threadIdx.x >> 5;

#pragma unroll
    for (int nn = 0; nn < 4; nn++) {
        int nl = nn * 8 + ty;
        int n = n0 + nl;
        size_t row = (size_t)(b * SEQ + n);
        size_t pb = row * NPROJ + k0 + tx;
        float pa  = g_proj[pb];
        float pw  = g_proj[pb + KCH];
        float pp  = g_proj[pb + 2 * KCH];
        float pal = g_proj[pb + 3 * KCH];
        float pg  = g_proj[pb + 4 * KCH];
        float pbe = g_proj[pb + 5 * KCH];

        float Aamp  = 3.0f * sigm(pa);
        float omega = softplusf(pw);
        float alpha = sigm(pal);
        float gg    = sigm(pg);
        float bee   = sigm(pbe);
        float pos   = log1pf((float)n);
        float angle = fmaf(omega, pos, pp);
        float sn, cs;
        sincosf(angle, &sn, &cs);

        size_t ob = row * KCH + k0 + tx;
        g_cosb[ob] = cs; g_sinb[ob] = sn; g_betab[ob] = bee; g_gb[ob] = gg;

        float oma = 1.0f - alpha;
        t_a [nl][tx] = alpha;
        t_dr[nl][tx] = oma * Aamp * cs;
        t_di[nl][tx] = oma * Aamp * sn;
    }
    __syncthreads();
#pragma unroll
    for (int nn = 0; nn < 4; nn++) {
        int kl = nn * 8 + ty;
        size_t ob = ((size_t)(b * KCH + k0 + kl)) * SEQ + n0 + tx;
        g_alpha[ob] = t_a [tx][kl];
        g_dr   [ob] = t_dr[tx][kl];
        g_di   [ob] = t_di[tx][kl];
    }
}

// ---------------- scan ------------------------------------------------------
__global__ __launch_bounds__(256) void scan_kernel() {
    __shared__ float s_a[CHUNK], s_br[CHUNK], s_bi[CHUNK];
    __shared__ float sc_a[256], sc_r[256], sc_i[256];

    int bk = blockIdx.x;
    int b = bk >> 8, k = bk & 255;
    size_t base = (size_t)bk * SEQ;
    int tid = threadIdx.x;
    float carry_r = 0.0f, carry_i = 0.0f;

    for (int c = 0; c < SEQ / CHUNK; c++) {
        for (int idx = tid; idx < CHUNK; idx += 256) {
            s_a [idx] = g_alpha[base + c * CHUNK + idx];
            s_br[idx] = g_dr   [base + c * CHUNK + idx];
            s_bi[idx] = g_di   [base + c * CHUNK + idx];
        }
        __syncthreads();

        int j0 = tid * 8;
        float Asg = 1.0f, Br = 0.0f, Bi = 0.0f;
#pragma unroll
        for (int j = 0; j < 8; j++) {
            float a = s_a[j0 + j];
            Asg *= a;
            Br = fmaf(a, Br, s_br[j0 + j]);
            Bi = fmaf(a, Bi, s_bi[j0 + j]);
        }
        sc_a[tid] = Asg; sc_r[tid] = Br; sc_i[tid] = Bi;
        __syncthreads();

        for (int off = 1; off < 256; off <<= 1) {
            float pa = 1.0f, pr = 0.0f, pi = 0.0f;
            if (tid >= off) { pa = sc_a[tid - off]; pr = sc_r[tid - off]; pi = sc_i[tid - off]; }
            float ca = sc_a[tid], cr = sc_r[tid], ci = sc_i[tid];
            __syncthreads();
            sc_a[tid] = pa * ca;
            sc_r[tid] = fmaf(ca, pr, cr);
            sc_i[tid] = fmaf(ca, pi, ci);
            __syncthreads();
        }

        float exa = (tid > 0) ? sc_a[tid - 1] : 1.0f;
        float exr = (tid > 0) ? sc_r[tid - 1] : 0.0f;
        float exi = (tid > 0) ? sc_i[tid - 1] : 0.0f;
        float rr = fmaf(exa, carry_r, exr);
        float ri = fmaf(exa, carry_i, exi);
        float ncr = fmaf(sc_a[255], carry_r, sc_r[255]);
        float nci = fmaf(sc_a[255], carry_i, sc_i[255]);

#pragma unroll
        for (int j = 0; j < 8; j++) {
            float a = s_a[j0 + j];
            rr = fmaf(a, rr, s_br[j0 + j]);
            ri = fmaf(a, ri, s_bi[j0 + j]);
            int n = c * CHUNK + j0 + j;
            size_t o = ((size_t)(b * SEQ + n)) * KCH + k;
            g_rr[o] = rr;
            g_ri[o] = ri;
        }
        carry_r = ncr; carry_i = nci;
        __syncthreads();
    }
}

// ---------------- postscan -> rho concatenated bf16 (A pattern) -------------
__device__ __forceinline__ void writeA(size_t base, int idx, float v) {
    __nv_bfloat16 h, l; bsplit(v, h, l);
    g_rhocat[base + idx]        = h;
    g_rhocat[base + 1024 + idx] = h;
    g_rhocat[base + 2048 + idx] = l;
}

__global__ __launch_bounds__(256) void postscan_kernel(const float* __restrict__ lam_ptr) {
    __shared__ float sre[256], simm[256], sgg[256];
    int row = blockIdx.x;
    int k = threadIdx.x;
    size_t o = (size_t)row * KCH + k;

    float rr = g_rr[o], ri = g_ri[o];
    float cs = g_cosb[o], sn = g_sinb[o];
    float be = g_betab[o], gg = g_gb[o];
    float pq = g_pq[o];

    float readout = fmaf(rr, cs, ri * sn);
    rr = fmaf(-be * readout, cs, rr);
    ri = fmaf(-be * readout, sn, ri);

    float mod = sqrtf(fmaf(rr, rr, fmaf(ri, ri, 1e-8f)));
    float scl = fmaxf(mod, 1.0f);
    rr /= scl; ri /= scl;

    float rre = fmaf(rr, cs, ri * sn);
    float rim = fmaf(-rr, sn, ri * cs);

    float rn = sqrtf(fmaf(rre, rre, fmaf(rim, rim, 1e-8f)));
    float ps, pc;
    sincosf(pq, &ps, &pc);
    float align = (rre * pc + rim * ps) / rn;
    float lam = *lam_ptr;
    float gate = 1.0f / (1.0f + expf(-lam * align));
    rre *= gate; rim *= gate;

    sre[k] = rre; simm[k] = rim; sgg[k] = gg;
    __syncthreads();

    size_t ob = (size_t)row * K3;
    writeA(ob, k, gg * rre);
    writeA(ob, 256 + k, gg * rim);
    if (k < 255) {
        float are = sre[k], aim = simm[k], bre = sre[k + 1], bim = simm[k + 1];
        float xre = are * bre - aim * bim;
        float xim = are * bim + aim * bre;
        float gc = 0.5f * (sgg[k] + sgg[k + 1]);
        writeA(ob, 512 + k, gc * xre);
        writeA(ob, 767 + k, gc * xim);
    } else {
        writeA(ob, 1022, 0.0f);
        writeA(ob, 1023, 0.0f);
    }
}

// ---------------- launch ---------------------------------------------------
extern "C" void kernel_launch(void* const* d_in, const int* in_sizes, int n_in,
                              void* d_out, int out_size) {
    const float* x   = (const float*)d_in[0];
    const float* Wp  = (const float*)d_in[1];
    const float* bp  = (const float*)d_in[2];
    const float* Wr  = (const float*)d_in[3];
    const float* Wph = (const float*)d_in[4];
    const float* bph = (const float*)d_in[5];
    const float* lam = (const float*)d_in[6];
    const float* rs  = (const float*)d_in[7];
    float* out = (float*)d_out;

    cudaFuncSetAttribute(mma_gemm, cudaFuncAttributeMaxDynamicSharedMemorySize, GSMEM);

    split_cat_kernel<<<(ROWS * DM / 4 + 255) / 256, 256>>>((const float4*)x,   ROWS * DM / 4, 0);
    split_cat_kernel<<<(NPROJ * DM / 4 + 255) / 256, 256>>>((const float4*)Wp,  NPROJ * DM / 4, 1);
    split_cat_kernel<<<(KCH * DM / 4 + 255) / 256, 256>>>((const float4*)Wph, KCH * DM / 4, 2);
    wres_split_cat_kernel<<<(DM * DM) / 256, 256>>>(Wr);

    // proj = x @ W_proj^T + b_proj
    mma_gemm<<<dim3(NPROJ / 128, ROWS / 128), 256, GSMEM>>>(bp, nullptr, nullptr, NPROJ, 0);
    // phase_query = x @ W_phase^T + b_phase
    mma_gemm<<<dim3(KCH / 128, ROWS / 128), 256, GSMEM>>>(bph, nullptr, nullptr, KCH, 1);

    prescan_kernel<<<4096, 256>>>();
    scan_kernel<<<BB * KCH, 256>>>();
    postscan_kernel<<<ROWS, 256>>>(lam);

    // out = res_scale * rho @ W_res^T
    mma_gemm<<<dim3(DM / 128, ROWS / 128), 256, GSMEM>>>(nullptr, rs, out, DM, 2);
}

// round 8
// speedup vs baseline: 2.7640x; 1.0810x over previous
#include <cuda_runtime.h>
#include <cuda_bf16.h>
#include <math.h>
#include <stdint.h>

#define BB 4
#define SEQ 4096
#define DM 1024
#define K3 3072                 // 3x split concatenated K
#define KB3 (K3*2)              // bytes per row (6144)
#define KCH 256
#define ROWS (BB*SEQ)           // 16384
#define NPROJ (6*KCH)           // 1536
#define CHUNK 2048

// GEMM tiling: 128(M) x 256(N), k-tile 64, 4-stage cp.async pipeline
#define TM 128
#define TN 256
#define STAGE_BYTES 49152       // A 16KB + B 32KB
#define NSTAGE 4
#define GSMEM (NSTAGE*STAGE_BYTES)   // 192 KB

// ---------------- scratch (global device memory, allocation-free) ----------
__device__ __align__(16) float g_proj [(size_t)ROWS*NPROJ];
__device__ __align__(16) float g_pq   [(size_t)ROWS*KCH];
__device__ __align__(16) float g_alpha[(size_t)BB*KCH*SEQ];
__device__ __align__(16) float g_dr   [(size_t)BB*KCH*SEQ];
__device__ __align__(16) float g_di   [(size_t)BB*KCH*SEQ];
__device__ __align__(16) float g_cosb [(size_t)ROWS*KCH];
__device__ __align__(16) float g_sinb [(size_t)ROWS*KCH];
__device__ __align__(16) float g_betab[(size_t)ROWS*KCH];
__device__ __align__(16) float g_gb   [(size_t)ROWS*KCH];
__device__ __align__(16) float g_rr   [(size_t)ROWS*KCH];
__device__ __align__(16) float g_ri   [(size_t)ROWS*KCH];

// bf16 concatenated-split operands: A pattern [hi|hi|lo], B pattern [hi|lo|hi]
__device__ __align__(16) __nv_bfloat16 g_xcat  [(size_t)ROWS*K3];
__device__ __align__(16) __nv_bfloat16 g_wpcat [(size_t)NPROJ*K3];
__device__ __align__(16) __nv_bfloat16 g_wqcat [(size_t)KCH*K3];
__device__ __align__(16) __nv_bfloat16 g_wrcat [(size_t)DM*K3];
__device__ __align__(16) __nv_bfloat16 g_rhocat[(size_t)ROWS*K3];

// ---------------- helpers --------------------------------------------------
__device__ __forceinline__ uint32_t smem_u32(const void* p) {
    uint32_t a;
    asm("{ .reg .u64 t; cvta.to.shared.u64 t, %1; cvt.u32.u64 %0, t; }" : "=r"(a) : "l"(p));
    return a;
}
__device__ __forceinline__ void cp16(uint32_t s, const void* g) {
    asm volatile("cp.async.cg.shared.global [%0], [%1], 16;" :: "r"(s), "l"(g) : "memory");
}
#define CP_COMMIT() asm volatile("cp.async.commit_group;" ::: "memory")

__device__ __forceinline__ void ldsm4(uint32_t* r, uint32_t addr) {
    asm volatile("ldmatrix.sync.aligned.m8n8.x4.shared.b16 {%0,%1,%2,%3}, [%4];"
                 : "=r"(r[0]), "=r"(r[1]), "=r"(r[2]), "=r"(r[3]) : "r"(addr));
}
__device__ __forceinline__ void mma16816(float* c, const uint32_t* a, const uint32_t* b) {
    asm volatile("mma.sync.aligned.m16n8k16.row.col.f32.bf16.bf16.f32 "
                 "{%0,%1,%2,%3}, {%4,%5,%6,%7}, {%8,%9}, {%0,%1,%2,%3};"
                 : "+f"(c[0]), "+f"(c[1]), "+f"(c[2]), "+f"(c[3])
                 : "r"(a[0]), "r"(a[1]), "r"(a[2]), "r"(a[3]), "r"(b[0]), "r"(b[1]));
}
__device__ __forceinline__ float sigm(float x) { return 1.0f / (1.0f + expf(-x)); }
__device__ __forceinline__ float softplusf(float x) { return (x > 20.0f) ? x : log1pf(expf(x)); }
__device__ __forceinline__ void bsplit(float v, __nv_bfloat16& h, __nv_bfloat16& l) {
    h = __float2bfloat16(v);
    l = __float2bfloat16(v - __bfloat162float(h));
}

// ---------------- split fp32 (rows x 1024) -> bf16 concatenated (rows x 3072)
__global__ void split_cat_kernel(const float4* __restrict__ src, int n4, int which) {
    int i = blockIdx.x * 256 + threadIdx.x;
    if (i >= n4) return;
    float4 v = src[i];
    __nv_bfloat16* dst = (which == 0) ? g_xcat : ((which == 1) ? g_wpcat : g_wqcat);
    int isA = (which == 0);
    int row = i >> 8, q = i & 255;
    size_t base = (size_t)row * K3 + q * 4;
    __nv_bfloat16 h[4], l[4];
    bsplit(v.x, h[0], l[0]); bsplit(v.y, h[1], l[1]);
    bsplit(v.z, h[2], l[2]); bsplit(v.w, h[3], l[3]);
#pragma unroll
    for (int j = 0; j < 4; j++) {
        dst[base + j]        = h[j];
        dst[base + 1024 + j] = isA ? h[j] : l[j];
        dst[base + 2048 + j] = isA ? l[j] : h[j];
    }
}

// W_res (1024 x 1022) -> padded, B pattern
__global__ void wres_split_cat_kernel(const float* __restrict__ W) {
    int i = blockIdx.x * 256 + threadIdx.x;       // 0 .. 1024*1024-1
    int d = i >> 10, j = i & 1023;
    float v = (j < 1022) ? W[(size_t)d * 1022 + j] : 0.0f;
    __nv_bfloat16 h, l; bsplit(v, h, l);
    size_t base = (size_t)d * K3;
    g_wrcat[base + j]        = h;
    g_wrcat[base + 1024 + j] = l;
    g_wrcat[base + 2048 + j] = h;
}

// ---------------- stage one 64-wide k-tile (A 128 rows, B 256 rows) --------
__device__ __forceinline__ void stage_tile(
    uint32_t sbase, const char* gA, const char* gB,
    uint32_t srow, uint32_t sseg, size_t kt_off)
{
    uint32_t sw = (sseg ^ (srow & 7)) * 16;
#pragma unroll
    for (int r = 0; r < 4; r++) {
        uint32_t row = srow + r * 32;
        cp16(sbase + row * 128 + sw, gA + kt_off + (size_t)row * KB3 + sseg * 16);
    }
#pragma unroll
    for (int r = 0; r < 8; r++) {
        uint32_t row = srow + r * 32;
        cp16(sbase + 16384 + row * 128 + sw, gB + kt_off + (size_t)row * KB3 + sseg * 16);
    }
}

// ---------------- HMMA GEMM: C[m,n] = sc * sum_k A[m,k]B[n,k] (+bias[n]) ----
// mode 0: A=g_xcat, B=g_wpcat, C=g_proj (Kd=3072)
// mode 1: A=g_xcat, B=g_wqcat, C=g_pq   (Kd=1024, single-term)
// mode 2: A=g_rhocat, B=g_wrcat, C=ext  (Kd=3072)
__global__ __launch_bounds__(256, 1) void mma_gemm(
    const float* __restrict__ bias, const float* __restrict__ scale_ptr,
    float* __restrict__ C_ext, int Nt, int Kd, int mode)
{
    extern __shared__ char smem[];
    const __nv_bfloat16 *A, *B; float* C;
    if (mode == 2)      { A = g_rhocat; B = g_wrcat; C = C_ext;  }
    else if (mode == 0) { A = g_xcat;   B = g_wpcat; C = g_proj; }
    else                { A = g_xcat;   B = g_wqcat; C = g_pq;   }

    uint32_t sb = smem_u32(smem);
    int tid = threadIdx.x, lane = tid & 31, wid = tid >> 5;
    int wm = wid >> 2, wn = wid & 3;               // warps 2(m) x 4(n), warp tile 64x64
    int m0 = blockIdx.y * TM, n0 = blockIdx.x * TN;
    int nkit = Kd >> 6;

    const char* gA = (const char*)A + (size_t)m0 * KB3;
    const char* gB = (const char*)B + (size_t)n0 * KB3;

    uint32_t srow = (uint32_t)(tid >> 3), sseg = (uint32_t)(tid & 7);

    // ldmatrix lane geometry
    int rowA = wm * 64 + (lane & 15);
    int segA = lane >> 4;
    int xorA = rowA & 7;
    int rowBin = (lane & 7) + ((lane >> 4) << 3);
    int segB = (lane >> 3) & 1;

    float acc[4][8][4];
#pragma unroll
    for (int mi = 0; mi < 4; mi++)
#pragma unroll
        for (int nj = 0; nj < 8; nj++)
#pragma unroll
            for (int q = 0; q < 4; q++) acc[mi][nj][q] = 0.0f;

    // prologue: stage k-tiles 0..2
#pragma unroll
    for (int s = 0; s < NSTAGE - 1; s++) {
        if (s < nkit) stage_tile(sb + s * STAGE_BYTES, gA, gB, srow, sseg, (size_t)s * 128);
        CP_COMMIT();
    }

    for (int kt = 0; kt < nkit; kt++) {
        asm volatile("cp.async.wait_group 2;" ::: "memory");
        __syncthreads();
        if (kt + 3 < nkit)
            stage_tile(sb + ((kt + 3) & 3) * STAGE_BYTES, gA, gB, srow, sseg,
                       (size_t)(kt + 3) * 128);
        CP_COMMIT();

        uint32_t bufA = sb + (kt & 3) * STAGE_BYTES;
        uint32_t bufB = bufA + 16384;
#pragma unroll
        for (int ks = 0; ks < 4; ks++) {
            uint32_t a[4][4], b[4][4];
#pragma unroll
            for (int mi = 0; mi < 4; mi++) {
                uint32_t addr = bufA + (uint32_t)(rowA + mi * 16) * 128
                              + (uint32_t)(((ks * 2 + segA) ^ xorA) * 16);
                ldsm4(a[mi], addr);
            }
#pragma unroll
            for (int j2 = 0; j2 < 4; j2++) {
                int rb = wn * 64 + j2 * 16 + rowBin;
                uint32_t addr = bufB + (uint32_t)rb * 128
                              + (uint32_t)(((ks * 2 + segB) ^ (rb & 7)) * 16);
                ldsm4(b[j2], addr);
            }
#pragma unroll
            for (int mi = 0; mi < 4; mi++) {
#pragma unroll
                for (int j2 = 0; j2 < 4; j2++) {
                    mma16816(acc[mi][j2 * 2],     a[mi], &b[j2][0]);
                    mma16816(acc[mi][j2 * 2 + 1], a[mi], &b[j2][2]);
                }
            }
        }
        __syncthreads();
    }

    // epilogue
    float sc = scale_ptr ? *scale_ptr : 1.0f;
#pragma unroll
    for (int mi = 0; mi < 4; mi++) {
#pragma unroll
        for (int nj = 0; nj < 8; nj++) {
            int row = m0 + wm * 64 + mi * 16 + (lane >> 2);
            int col = n0 + wn * 64 + nj * 8 + (lane & 3) * 2;
            float b0 = 0.0f, b1 = 0.0f;
            if (bias) { b0 = bias[col]; b1 = bias[col + 1]; }
            float2 v0 = make_float2(acc[mi][nj][0] * sc + b0, acc[mi][nj][1] * sc + b1);
            float2 v1 = make_float2(acc[mi][nj][2] * sc + b0, acc[mi][nj][3] * sc + b1);
            *(float2*)(C + (size_t)row * Nt + col)       = v0;
            *(float2*)(C + (size_t)(row + 8) * Nt + col) = v1;
        }
    }
}

// ---------------- prescan: activations + transpose for the scan -----------
__global__ __launch_bounds__(256) void prescan_kernel() {
    __shared__ float t_a [32][33];
    __shared__ float t_dr[32][33];
    __shared__ float t_di[32][33];

    int bk = blockIdx.x;
    int kb = bk & 7, nb = (bk >> 3) & 127, b = bk >> 10;
    int k0 = kb * 32, n0 = nb * 32;
    int tx = threadIdx.x & 31;
    int ty = threadIdx.x >> 5;

#pragma unroll
    for (int nn = 0; nn < 4; nn++) {
        int nl = nn * 8 + ty;
        int n = n0 + nl;
        size_t row = (size_t)(b * SEQ + n);
        size_t pb = row * NPROJ + k0 + tx;
        float pa  = g_proj[pb];
        float pw  = g_proj[pb + KCH];
        float pp  = g_proj[pb + 2 * KCH];
        float pal = g_proj[pb + 3 * KCH];
        float pg  = g_proj[pb + 4 * KCH];
        float pbe = g_proj[pb + 5 * KCH];

        float Aamp  = 3.0f * sigm(pa);
        float omega = softplusf(pw);
        float alpha = sigm(pal);
        float gg    = sigm(pg);
        float bee   = sigm(pbe);
        float pos   = log1pf((float)n);
        float angle = fmaf(omega, pos, pp);
        float sn, cs;
        sincosf(angle, &sn, &cs);

        size_t ob = row * KCH + k0 + tx;
        g_cosb[ob] = cs; g_sinb[ob] = sn; g_betab[ob] = bee; g_gb[ob] = gg;

        float oma = 1.0f - alpha;
        t_a [nl][tx] = alpha;
        t_dr[nl][tx] = oma * Aamp * cs;
        t_di[nl][tx] = oma * Aamp * sn;
    }
    __syncthreads();
#pragma unroll
    for (int nn = 0; nn < 4; nn++) {
        int kl = nn * 8 + ty;
        size_t ob = ((size_t)(b * KCH + k0 + kl)) * SEQ + n0 + tx;
        g_alpha[ob] = t_a [tx][kl];
        g_dr   [ob] = t_dr[tx][kl];
        g_di   [ob] = t_di[tx][kl];
    }
}

// ---------------- scan ------------------------------------------------------
__global__ __launch_bounds__(256) void scan_kernel() {
    __shared__ float s_a[CHUNK], s_br[CHUNK], s_bi[CHUNK];
    __shared__ float sc_a[256], sc_r[256], sc_i[256];

    int bk = blockIdx.x;
    int b = bk >> 8, k = bk & 255;
    size_t base = (size_t)bk * SEQ;
    int tid = threadIdx.x;
    float carry_r = 0.0f, carry_i = 0.0f;

    for (int c = 0; c < SEQ / CHUNK; c++) {
        for (int idx = tid; idx < CHUNK; idx += 256) {
            s_a [idx] = g_alpha[base + c * CHUNK + idx];
            s_br[idx] = g_dr   [base + c * CHUNK + idx];
            s_bi[idx] = g_di   [base + c * CHUNK + idx];
        }
        __syncthreads();

        int j0 = tid * 8;
        float Asg = 1.0f, Br = 0.0f, Bi = 0.0f;
#pragma unroll
        for (int j = 0; j < 8; j++) {
            float a = s_a[j0 + j];
            Asg *= a;
            Br = fmaf(a, Br, s_br[j0 + j]);
            Bi = fmaf(a, Bi, s_bi[j0 + j]);
        }
        sc_a[tid] = Asg; sc_r[tid] = Br; sc_i[tid] = Bi;
        __syncthreads();

        for (int off = 1; off < 256; off <<= 1) {
            float pa = 1.0f, pr = 0.0f, pi = 0.0f;
            if (tid >= off) { pa = sc_a[tid - off]; pr = sc_r[tid - off]; pi = sc_i[tid - off]; }
            float ca = sc_a[tid], cr = sc_r[tid], ci = sc_i[tid];
            __syncthreads();
            sc_a[tid] = pa * ca;
            sc_r[tid] = fmaf(ca, pr, cr);
            sc_i[tid] = fmaf(ca, pi, ci);
            __syncthreads();
        }

        float exa = (tid > 0) ? sc_a[tid - 1] : 1.0f;
        float exr = (tid > 0) ? sc_r[tid - 1] : 0.0f;
        float exi = (tid > 0) ? sc_i[tid - 1] : 0.0f;
        float rr = fmaf(exa, carry_r, exr);
        float ri = fmaf(exa, carry_i, exi);
        float ncr = fmaf(sc_a[255], carry_r, sc_r[255]);
        float nci = fmaf(sc_a[255], carry_i, sc_i[255]);

#pragma unroll
        for (int j = 0; j < 8; j++) {
            float a = s_a[j0 + j];
            rr = fmaf(a, rr, s_br[j0 + j]);
            ri = fmaf(a, ri, s_bi[j0 + j]);
            int n = c * CHUNK + j0 + j;
            size_t o = ((size_t)(b * SEQ + n)) * KCH + k;
            g_rr[o] = rr;
            g_ri[o] = ri;
        }
        carry_r = ncr; carry_i = nci;
        __syncthreads();
    }
}

// ---------------- postscan -> rho concatenated bf16 (A pattern) -------------
__device__ __forceinline__ void writeA(size_t base, int idx, float v) {
    __nv_bfloat16 h, l; bsplit(v, h, l);
    g_rhocat[base + idx]        = h;
    g_rhocat[base + 1024 + idx] = h;
    g_rhocat[base + 2048 + idx] = l;
}

__global__ __launch_bounds__(256) void postscan_kernel(const float* __restrict__ lam_ptr) {
    __shared__ float sre[256], simm[256], sgg[256];
    int row = blockIdx.x;
    int k = threadIdx.x;
    size_t o = (size_t)row * KCH + k;

    float rr = g_rr[o], ri = g_ri[o];
    float cs = g_cosb[o], sn = g_sinb[o];
    float be = g_betab[o], gg = g_gb[o];
    float pq = g_pq[o];

    float readout = fmaf(rr, cs, ri * sn);
    rr = fmaf(-be * readout, cs, rr);
    ri = fmaf(-be * readout, sn, ri);

    float mod = sqrtf(fmaf(rr, rr, fmaf(ri, ri, 1e-8f)));
    float scl = fmaxf(mod, 1.0f);
    rr /= scl; ri /= scl;

    float rre = fmaf(rr, cs, ri * sn);
    float rim = fmaf(-rr, sn, ri * cs);

    float rn = sqrtf(fmaf(rre, rre, fmaf(rim, rim, 1e-8f)));
    float ps, pc;
    sincosf(pq, &ps, &pc);
    float align = (rre * pc + rim * ps) / rn;
    float lam = *lam_ptr;
    float gate = 1.0f / (1.0f + expf(-lam * align));
    rre *= gate; rim *= gate;

    sre[k] = rre; simm[k] = rim; sgg[k] = gg;
    __syncthreads();

    size_t ob = (size_t)row * K3;
    writeA(ob, k, gg * rre);
    writeA(ob, 256 + k, gg * rim);
    if (k < 255) {
        float are = sre[k], aim = simm[k], bre = sre[k + 1], bim = simm[k + 1];
        float xre = are * bre - aim * bim;
        float xim = are * bim + aim * bre;
        float gc = 0.5f * (sgg[k] + sgg[k + 1]);
        writeA(ob, 512 + k, gc * xre);
        writeA(ob, 767 + k, gc * xim);
    } else {
        writeA(ob, 1022, 0.0f);
        writeA(ob, 1023, 0.0f);
    }
}

// ---------------- launch ---------------------------------------------------
extern "C" void kernel_launch(void* const* d_in, const int* in_sizes, int n_in,
                              void* d_out, int out_size) {
    const float* x   = (const float*)d_in[0];
    const float* Wp  = (const float*)d_in[1];
    const float* bp  = (const float*)d_in[2];
    const float* Wr  = (const float*)d_in[3];
    const float* Wph = (const float*)d_in[4];
    const float* bph = (const float*)d_in[5];
    const float* lam = (const float*)d_in[6];
    const float* rs  = (const float*)d_in[7];
    float* out = (float*)d_out;

    cudaFuncSetAttribute(mma_gemm, cudaFuncAttributeMaxDynamicSharedMemorySize, GSMEM);

    split_cat_kernel<<<(ROWS * DM / 4 + 255) / 256, 256>>>((const float4*)x,   ROWS * DM / 4, 0);
    split_cat_kernel<<<(NPROJ * DM / 4 + 255) / 256, 256>>>((const float4*)Wp,  NPROJ * DM / 4, 1);
    split_cat_kernel<<<(KCH * DM / 4 + 255) / 256, 256>>>((const float4*)Wph, KCH * DM / 4, 2);
    wres_split_cat_kernel<<<(DM * DM) / 256, 256>>>(Wr);

    // proj = x @ W_proj^T + b_proj   (3-term split, K=3072)
    mma_gemm<<<dim3(NPROJ / TN, ROWS / TM), 256, GSMEM>>>(bp, nullptr, nullptr, NPROJ, K3, 0);
    // phase_query = x @ W_phase^T + b_phase  (single bf16, K=1024)
    mma_gemm<<<dim3(KCH / TN, ROWS / TM), 256, GSMEM>>>(bph, nullptr, nullptr, KCH, DM, 1);

    prescan_kernel<<<4096, 256>>>();
    scan_kernel<<<BB * KCH, 256>>>();
    postscan_kernel<<<ROWS, 256>>>(lam);

    // out = res_scale * rho @ W_res^T  (3-term split, K=3072)
    mma_gemm<<<dim3(DM / TN, ROWS / TM), 256, GSMEM>>>(nullptr, rs, out, DM, K3, 2);
}

// round 11
// speedup vs baseline: 3.1078x; 1.1244x over previous
#include <cuda_runtime.h>
#include <cuda_bf16.h>
#include <math.h>
#include <stdint.h>

#define BB 4
#define SEQ 4096
#define DM 1024
#define K3 3072                 // 3x split concatenated K
#define KB3 (K3*2)              // bytes per row (6144)
#define KCH 256
#define ROWS (BB*SEQ)           // 16384
#define NPROJ (6*KCH)           // 1536
#define CHUNK 2048

// GEMM tiling: 128(M) x 128(N), k-tile 64, 3-stage cp.async pipeline, 2 CTA/SM
#define TM 128
#define TN 128
#define STAGE_BYTES 32768       // A 16KB + B 16KB
#define NSTAGE 3
#define GSMEM (NSTAGE*STAGE_BYTES)   // 96 KB

// ---------------- scratch (global device memory, allocation-free) ----------
__device__ __align__(16) float g_proj [(size_t)ROWS*NPROJ];
__device__ __align__(16) float g_pq   [(size_t)ROWS*KCH];
__device__ __align__(16) float g_alpha[(size_t)BB*KCH*SEQ];
__device__ __align__(16) float g_dr   [(size_t)BB*KCH*SEQ];
__device__ __align__(16) float g_di   [(size_t)BB*KCH*SEQ];
__device__ __align__(16) float g_cosb [(size_t)ROWS*KCH];
__device__ __align__(16) float g_sinb [(size_t)ROWS*KCH];
__device__ __align__(16) float g_betab[(size_t)ROWS*KCH];
__device__ __align__(16) float g_gb   [(size_t)ROWS*KCH];
__device__ __align__(16) float g_rr   [(size_t)ROWS*KCH];
__device__ __align__(16) float g_ri   [(size_t)ROWS*KCH];

// bf16 concatenated-split operands: A pattern [hi|hi|lo], B pattern [hi|lo|hi]
__device__ __align__(16) __nv_bfloat16 g_xcat  [(size_t)ROWS*K3];
__device__ __align__(16) __nv_bfloat16 g_wpcat [(size_t)NPROJ*K3];
__device__ __align__(16) __nv_bfloat16 g_wqcat [(size_t)KCH*K3];
__device__ __align__(16) __nv_bfloat16 g_wrcat [(size_t)DM*K3];
__device__ __align__(16) __nv_bfloat16 g_rhocat[(size_t)ROWS*K3];

// ---------------- helpers --------------------------------------------------
__device__ __forceinline__ uint32_t smem_u32(const void* p) {
    uint32_t a;
    asm("{ .reg .u64 t; cvta.to.shared.u64 t, %1; cvt.u32.u64 %0, t; }" : "=r"(a) : "l"(p));
    return a;
}
__device__ __forceinline__ void cp16(uint32_t s, const void* g) {
    asm volatile("cp.async.cg.shared.global [%0], [%1], 16;" :: "r"(s), "l"(g) : "memory");
}
#define CP_COMMIT() asm volatile("cp.async.commit_group;" ::: "memory")

__device__ __forceinline__ void ldsm4(uint32_t* r, uint32_t addr) {
    asm volatile("ldmatrix.sync.aligned.m8n8.x4.shared.b16 {%0,%1,%2,%3}, [%4];"
                 : "=r"(r[0]), "=r"(r[1]), "=r"(r[2]), "=r"(r[3]) : "r"(addr));
}
__device__ __forceinline__ void mma16816(float* c, const uint32_t* a, const uint32_t* b) {
    asm volatile("mma.sync.aligned.m16n8k16.row.col.f32.bf16.bf16.f32 "
                 "{%0,%1,%2,%3}, {%4,%5,%6,%7}, {%8,%9}, {%0,%1,%2,%3};"
                 : "+f"(c[0]), "+f"(c[1]), "+f"(c[2]), "+f"(c[3])
                 : "r"(a[0]), "r"(a[1]), "r"(a[2]), "r"(a[3]), "r"(b[0]), "r"(b[1]));
}
__device__ __forceinline__ float sigm(float x) { return 1.0f / (1.0f + expf(-x)); }
__device__ __forceinline__ float softplusf(float x) { return (x > 20.0f) ? x : log1pf(expf(x)); }
__device__ __forceinline__ void bsplit(float v, __nv_bfloat16& h, __nv_bfloat16& l) {
    h = __float2bfloat16(v);
    l = __float2bfloat16(v - __bfloat162float(h));
}

// ---------------- split fp32 (rows x 1024) -> bf16 concatenated (rows x 3072)
__global__ void split_cat_kernel(const float4* __restrict__ src, int n4, int which) {
    int i = blockIdx.x * 256 + threadIdx.x;
    if (i >= n4) return;
    float4 v = src[i];
    __nv_bfloat16* dst = (which == 0) ? g_xcat : ((which == 1) ? g_wpcat : g_wqcat);
    int isA = (which == 0);
    int row = i >> 8, q = i & 255;
    size_t base = (size_t)row * K3 + q * 4;
    __nv_bfloat16 h[4], l[4];
    bsplit(v.x, h[0], l[0]); bsplit(v.y, h[1], l[1]);
    bsplit(v.z, h[2], l[2]); bsplit(v.w, h[3], l[3]);
#pragma unroll
    for (int j = 0; j < 4; j++) {
        dst[base + j]        = h[j];
        dst[base + 1024 + j] = isA ? h[j] : l[j];
        dst[base + 2048 + j] = isA ? l[j] : h[j];
    }
}

// W_res (1024 x 1022) -> padded, B pattern
__global__ void wres_split_cat_kernel(const float* __restrict__ W) {
    int i = blockIdx.x * 256 + threadIdx.x;       // 0 .. 1024*1024-1
    int d = i >> 10, j = i & 1023;
    float v = (j < 1022) ? W[(size_t)d * 1022 + j] : 0.0f;
    __nv_bfloat16 h, l; bsplit(v, h, l);
    size_t base = (size_t)d * K3;
    g_wrcat[base + j]        = h;
    g_wrcat[base + 1024 + j] = l;
    g_wrcat[base + 2048 + j] = h;
}

// ---------------- stage one 64-wide k-tile (A 128 rows, B 128 rows) --------
__device__ __forceinline__ void stage_tile(
    uint32_t sbase, const char* gA, const char* gB,
    uint32_t srow, uint32_t sseg, size_t kt_off)
{
    uint32_t sw = (sseg ^ (srow & 7)) * 16;
#pragma unroll
    for (int r = 0; r < 4; r++) {
        uint32_t row = srow + r * 32;
        cp16(sbase + row * 128 + sw, gA + kt_off + (size_t)row * KB3 + sseg * 16);
    }
#pragma unroll
    for (int r = 0; r < 4; r++) {
        uint32_t row = srow + r * 32;
        cp16(sbase + 16384 + row * 128 + sw, gB + kt_off + (size_t)row * KB3 + sseg * 16);
    }
}

// ---------------- HMMA GEMM: C[m,n] = sc * sum_k A[m,k]B[n,k] (+bias[n]) ----
// mode 0: A=g_xcat, B=g_wpcat, C=g_proj (Kd=3072)
// mode 1: A=g_xcat, B=g_wqcat, C=g_pq   (Kd=1024, single-term)
// mode 2: A=g_rhocat, B=g_wrcat, C=ext  (Kd=3072)
__global__ __launch_bounds__(256, 2) void mma_gemm(
    const float* __restrict__ bias, const float* __restrict__ scale_ptr,
    float* __restrict__ C_ext, int Nt, int Kd, int mode)
{
    extern __shared__ char smem[];
    const __nv_bfloat16 *A, *B; float* C;
    if (mode == 2)      { A = g_rhocat; B = g_wrcat; C = C_ext;  }
    else if (mode == 0) { A = g_xcat;   B = g_wpcat; C = g_proj; }
    else                { A = g_xcat;   B = g_wqcat; C = g_pq;   }

    uint32_t sb = smem_u32(smem);
    int tid = threadIdx.x, lane = tid & 31, wid = tid >> 5;
    int wm = wid >> 2, wn = wid & 3;               // warps 2(m) x 4(n), warp tile 64x32
    int m0 = blockIdx.y * TM, n0 = blockIdx.x * TN;
    int nkit = Kd >> 6;

    const char* gA = (const char*)A + (size_t)m0 * KB3;
    const char* gB = (const char*)B + (size_t)n0 * KB3;

    uint32_t srow = (uint32_t)(tid >> 3), sseg = (uint32_t)(tid & 7);

    // ldmatrix lane geometry
    int rowA = wm * 64 + (lane & 15);
    int segA = lane >> 4;
    int xorA = rowA & 7;
    int rowBin = (lane & 7) + ((lane >> 4) << 3);
    int segB = (lane >> 3) & 1;

    float acc[4][4][4];
#pragma unroll
    for (int mi = 0; mi < 4; mi++)
#pragma unroll
        for (int nj = 0; nj < 4; nj++)
#pragma unroll
            for (int q = 0; q < 4; q++) acc[mi][nj][q] = 0.0f;

    // prologue: stage k-tiles 0..1
#pragma unroll
    for (int s = 0; s < NSTAGE - 1; s++) {
        if (s < nkit) stage_tile(sb + s * STAGE_BYTES, gA, gB, srow, sseg, (size_t)s * 128);
        CP_COMMIT();
    }

    int buf = 0;
    for (int kt = 0; kt < nkit; kt++) {
        asm volatile("cp.async.wait_group 1;" ::: "memory");
        __syncthreads();
        if (kt + 2 < nkit) {
            int pb = buf + 2; if (pb >= NSTAGE) pb -= NSTAGE;
            stage_tile(sb + pb * STAGE_BYTES, gA, gB, srow, sseg, (size_t)(kt + 2) * 128);
        }
        CP_COMMIT();

        uint32_t bufA = sb + buf * STAGE_BYTES;
        uint32_t bufB = bufA + 16384;
#pragma unroll
        for (int ks = 0; ks < 4; ks++) {
            uint32_t a[4][4], b[2][4];
#pragma unroll
            for (int mi = 0; mi < 4; mi++) {
                uint32_t addr = bufA + (uint32_t)(rowA + mi * 16) * 128
                              + (uint32_t)(((ks * 2 + segA) ^ xorA) * 16);
                ldsm4(a[mi], addr);
            }
#pragma unroll
            for (int j2 = 0; j2 < 2; j2++) {
                int rb = wn * 32 + j2 * 16 + rowBin;
                uint32_t addr = bufB + (uint32_t)rb * 128
                              + (uint32_t)(((ks * 2 + segB) ^ (rb & 7)) * 16);
                ldsm4(b[j2], addr);
            }
#pragma unroll
            for (int mi = 0; mi < 4; mi++) {
#pragma unroll
                for (int j2 = 0; j2 < 2; j2++) {
                    mma16816(acc[mi][j2 * 2],     a[mi], &b[j2][0]);
                    mma16816(acc[mi][j2 * 2 + 1], a[mi], &b[j2][2]);
                }
            }
        }
        __syncthreads();
        if (++buf == NSTAGE) buf = 0;
    }

    // epilogue
    float sc = scale_ptr ? *scale_ptr : 1.0f;
#pragma unroll
    for (int mi = 0; mi < 4; mi++) {
#pragma unroll
        for (int nj = 0; nj < 4; nj++) {
            int row = m0 + wm * 64 + mi * 16 + (lane >> 2);
            int col = n0 + wn * 32 + nj * 8 + (lane & 3) * 2;
            float b0 = 0.0f, b1 = 0.0f;
            if (bias) { b0 = bias[col]; b1 = bias[col + 1]; }
            float2 v0 = make_float2(acc[mi][nj][0] * sc + b0, acc[mi][nj][1] * sc + b1);
            float2 v1 = make_float2(acc[mi][nj][2] * sc + b0, acc[mi][nj][3] * sc + b1);
            *(float2*)(C + (size_t)row * Nt + col)       = v0;
            *(float2*)(C + (size_t)(row + 8) * Nt + col) = v1;
        }
    }
}

// ---------------- prescan: activations + transpose for the scan -----------
__global__ __launch_bounds__(256) void prescan_kernel() {
    __shared__ float t_a [32][33];
    __shared__ float t_dr[32][33];
    __shared__ float t_di[32][33];

    int bk = blockIdx.x;
    int kb = bk & 7, nb = (bk >> 3) & 127, b = bk >> 10;
    int k0 = kb * 32, n0 = nb * 32;
    int tx = threadIdx.x & 31;
    int ty = threadIdx.x >> 5;

#pragma unroll
    for (int nn = 0; nn < 4; nn++) {
        int nl = nn * 8 + ty;
        int n = n0 + nl;
        size_t row = (size_t)(b * SEQ + n);
        size_t pb = row * NPROJ + k0 + tx;
        float pa  = g_proj[pb];
        float pw  = g_proj[pb + KCH];
        float pp  = g_proj[pb + 2 * KCH];
        float pal = g_proj[pb + 3 * KCH];
        float pg  = g_proj[pb + 4 * KCH];
        float pbe = g_proj[pb + 5 * KCH];

        float Aamp  = 3.0f * sigm(pa);
        float omega = softplusf(pw);
        float alpha = sigm(pal);
        float gg    = sigm(pg);
        float bee   = sigm(pbe);
        float pos   = log1pf((float)n);
        float angle = fmaf(omega, pos, pp);
        float sn, cs;
        sincosf(angle, &sn, &cs);

        size_t ob = row * KCH + k0 + tx;
        g_cosb[ob] = cs; g_sinb[ob] = sn; g_betab[ob] = bee; g_gb[ob] = gg;

        float oma = 1.0f - alpha;
        t_a [nl][tx] = alpha;
        t_dr[nl][tx] = oma * Aamp * cs;
        t_di[nl][tx] = oma * Aamp * sn;
    }
    __syncthreads();
#pragma unroll
    for (int nn = 0; nn < 4; nn++) {
        int kl = nn * 8 + ty;
        size_t ob = ((size_t)(b * KCH + k0 + kl)) * SEQ + n0 + tx;
        g_alpha[ob] = t_a [tx][kl];
        g_dr   [ob] = t_dr[tx][kl];
        g_di   [ob] = t_di[tx][kl];
    }
}

// ---------------- scan ------------------------------------------------------
__global__ __launch_bounds__(256) void scan_kernel() {
    __shared__ float s_a[CHUNK], s_br[CHUNK], s_bi[CHUNK];
    __shared__ float sc_a[256], sc_r[256], sc_i[256];

    int bk = blockIdx.x;
    int b = bk >> 8, k = bk & 255;
    size_t base = (size_t)bk * SEQ;
    int tid = threadIdx.x;
    float carry_r = 0.0f, carry_i = 0.0f;

    for (int c = 0; c < SEQ / CHUNK; c++) {
        for (int idx = tid; idx < CHUNK; idx += 256) {
            s_a [idx] = g_alpha[base + c * CHUNK + idx];
            s_br[idx] = g_dr   [base + c * CHUNK + idx];
            s_bi[idx] = g_di   [base + c * CHUNK + idx];
        }
        __syncthreads();

        int j0 = tid * 8;
        float Asg = 1.0f, Br = 0.0f, Bi = 0.0f;
#pragma unroll
        for (int j = 0; j < 8; j++) {
            float a = s_a[j0 + j];
            Asg *= a;
            Br = fmaf(a, Br, s_br[j0 + j]);
            Bi = fmaf(a, Bi, s_bi[j0 + j]);
        }
        sc_a[tid] = Asg; sc_r[tid] = Br; sc_i[tid] = Bi;
        __syncthreads();

        for (int off = 1; off < 256; off <<= 1) {
            float pa = 1.0f, pr = 0.0f, pi = 0.0f;
            if (tid >= off) { pa = sc_a[tid - off]; pr = sc_r[tid - off]; pi = sc_i[tid - off]; }
            float ca = sc_a[tid], cr = sc_r[tid], ci = sc_i[tid];
            __syncthreads();
            sc_a[tid] = pa * ca;
            sc_r[tid] = fmaf(ca, pr, cr);
            sc_i[tid] = fmaf(ca, pi, ci);
            __syncthreads();
        }

        float exa = (tid > 0) ? sc_a[tid - 1] : 1.0f;
        float exr = (tid > 0) ? sc_r[tid - 1] : 0.0f;
        float exi = (tid > 0) ? sc_i[tid - 1] : 0.0f;
        float rr = fmaf(exa, carry_r, exr);
        float ri = fmaf(exa, carry_i, exi);
        float ncr = fmaf(sc_a[255], carry_r, sc_r[255]);
        float nci = fmaf(sc_a[255], carry_i, sc_i[255]);

#pragma unroll
        for (int j = 0; j < 8; j++) {
            float a = s_a[j0 + j];
            rr = fmaf(a, rr, s_br[j0 + j]);
            ri = fmaf(a, ri, s_bi[j0 + j]);
            int n = c * CHUNK + j0 + j;
            size_t o = ((size_t)(b * SEQ + n)) * KCH + k;
            g_rr[o] = rr;
            g_ri[o] = ri;
        }
        carry_r = ncr; carry_i = nci;
        __syncthreads();
    }
}

// ---------------- postscan -> rho concatenated bf16 (A pattern) -------------
__device__ __forceinline__ void writeA(size_t base, int idx, float v) {
    __nv_bfloat16 h, l; bsplit(v, h, l);
    g_rhocat[base + idx]        = h;
    g_rhocat[base + 1024 + idx] = h;
    g_rhocat[base + 2048 + idx] = l;
}

__global__ __launch_bounds__(256) void postscan_kernel(const float* __restrict__ lam_ptr) {
    __shared__ float sre[256], simm[256], sgg[256];
    int row = blockIdx.x;
    int k = threadIdx.x;
    size_t o = (size_t)row * KCH + k;

    float rr = g_rr[o], ri = g_ri[o];
    float cs = g_cosb[o], sn = g_sinb[o];
    float be = g_betab[o], gg = g_gb[o];
    float pq = g_pq[o];

    float readout = fmaf(rr, cs, ri * sn);
    rr = fmaf(-be * readout, cs, rr);
    ri = fmaf(-be * readout, sn, ri);

    float mod = sqrtf(fmaf(rr, rr, fmaf(ri, ri, 1e-8f)));
    float scl = fmaxf(mod, 1.0f);
    rr /= scl; ri /= scl;

    float rre = fmaf(rr, cs, ri * sn);
    float rim = fmaf(-rr, sn, ri * cs);

    float rn = sqrtf(fmaf(rre, rre, fmaf(rim, rim, 1e-8f)));
    float ps, pc;
    sincosf(pq, &ps, &pc);
    float align = (rre * pc + rim * ps) / rn;
    float lam = *lam_ptr;
    float gate = 1.0f / (1.0f + expf(-lam * align));
    rre *= gate; rim *= gate;

    sre[k] = rre; simm[k] = rim; sgg[k] = gg;
    __syncthreads();

    size_t ob = (size_t)row * K3;
    writeA(ob, k, gg * rre);
    writeA(ob, 256 + k, gg * rim);
    if (k < 255) {
        float are = sre[k], aim = simm[k], bre = sre[k + 1], bim = simm[k + 1];
        float xre = are * bre - aim * bim;
        float xim = are * bim + aim * bre;
        float gc = 0.5f * (sgg[k] + sgg[k + 1]);
        writeA(ob, 512 + k, gc * xre);
        writeA(ob, 767 + k, gc * xim);
    } else {
        writeA(ob, 1022, 0.0f);
        writeA(ob, 1023, 0.0f);
    }
}

// ---------------- launch ---------------------------------------------------
extern "C" void kernel_launch(void* const* d_in, const int* in_sizes, int n_in,
                              void* d_out, int out_size) {
    const float* x   = (const float*)d_in[0];
    const float* Wp  = (const float*)d_in[1];
    const float* bp  = (const float*)d_in[2];
    const float* Wr  = (const float*)d_in[3];
    const float* Wph = (const float*)d_in[4];
    const float* bph = (const float*)d_in[5];
    const float* lam = (const float*)d_in[6];
    const float* rs  = (const float*)d_in[7];
    float* out = (float*)d_out;

    cudaFuncSetAttribute(mma_gemm, cudaFuncAttributeMaxDynamicSharedMemorySize, GSMEM);

    split_cat_kernel<<<(ROWS * DM / 4 + 255) / 256, 256>>>((const float4*)x,   ROWS * DM / 4, 0);
    split_cat_kernel<<<(NPROJ * DM / 4 + 255) / 256, 256>>>((const float4*)Wp,  NPROJ * DM / 4, 1);
    split_cat_kernel<<<(KCH * DM / 4 + 255) / 256, 256>>>((const float4*)Wph, KCH * DM / 4, 2);
    wres_split_cat_kernel<<<(DM * DM) / 256, 256>>>(Wr);

    // proj = x @ W_proj^T + b_proj   (3-term split, K=3072)
    mma_gemm<<<dim3(NPROJ / TN, ROWS / TM), 256, GSMEM>>>(bp, nullptr, nullptr, NPROJ, K3, 0);
    // phase_query = x @ W_phase^T + b_phase  (single bf16, K=1024)
    mma_gemm<<<dim3(KCH / TN, ROWS / TM), 256, GSMEM>>>(bph, nullptr, nullptr, KCH, DM, 1);

    prescan_kernel<<<4096, 256>>>();
    scan_kernel<<<BB * KCH, 256>>>();
    postscan_kernel<<<ROWS, 256>>>(lam);

    // out = res_scale * rho @ W_res^T  (3-term split, K=3072)
    mma_gemm<<<dim3(DM / TN, ROWS / TM), 256, GSMEM>>>(nullptr, rs, out, DM, K3, 2);
}